// round 13
// baseline (speedup 1.0000x reference)
#include <cuda_runtime.h>
#include <cuda_fp16.h>
#include <cuda.h>
#include <cstdint>

// Problem dims (fixed by the dataset)
constexpr int TT = 4096;    // tokens
constexpr int KK = 4096;    // in_features
constexpr int II = 11008;   // intermediate
constexpr int OO = 4096;    // out_features

constexpr int NS = 4;                    // pipeline stages
constexpr uint32_t GU_STAGE = 49152;     // A 32K | Bg 8K | Bu 8K
constexpr uint32_t DN_STAGE = 49152;     // A 32K | B0 8K | B1 8K
constexpr int SMEM_BYTES = 1024 + NS * 49152;  // 197632

// ---------------- device scratch ----------------
__device__ __align__(256) __half g_Wg[(size_t)KK * II];
__device__ __align__(256) __half g_Wu[(size_t)KK * II];
__device__ __align__(256) __half g_Wd[(size_t)II * OO];
__device__ __align__(256) __half g_X [(size_t)TT * KK];
__device__ __align__(256) __half g_H [(size_t)TT * II];

// ---------------- PTX helpers ----------------
__device__ __forceinline__ uint32_t smem_u32(const void* p) {
    return (uint32_t)__cvta_generic_to_shared(p);
}

#define MBAR_INIT(addr, cnt) \
    asm volatile("mbarrier.init.shared.b64 [%0], %1;" :: "r"(addr), "r"(cnt) : "memory")

#define MBAR_EXPECT_TX(addr, bytes) \
    asm volatile("mbarrier.arrive.expect_tx.shared.b64 _, [%0], %1;" :: "r"(addr), "r"(bytes) : "memory")

#define MBAR_ARRIVE(addr) \
    asm volatile("mbarrier.arrive.shared.b64 _, [%0];" :: "r"(addr) : "memory")

#define MBAR_WAIT(addr, par) do {                                                       \
    uint32_t _m = (addr); uint32_t _p = (par); uint32_t _d;                             \
    asm volatile("{\n .reg .pred p;\n"                                                  \
        " mbarrier.try_wait.parity.acquire.cta.shared::cta.b64 p, [%1], %2;\n"          \
        " selp.b32 %0, 1, 0, p;\n}"                                                     \
        : "=r"(_d) : "r"(_m), "r"(_p) : "memory");                                      \
    if (!_d) {                                                                          \
        asm volatile("{\n .reg .pred P1;\n"                                             \
            "WL_%=:\n"                                                                  \
            " mbarrier.try_wait.parity.acquire.cta.shared::cta.b64 P1, [%0], %1, 0x989680;\n" \
            " @P1 bra.uni WD_%=;\n bra.uni WL_%=;\nWD_%=:\n}"                           \
            :: "r"(_m), "r"(_p) : "memory");                                            \
    }                                                                                   \
} while (0)

#define MBAR_WAIT_RLX(addr, par) do {                                                   \
    uint32_t _m = (addr); uint32_t _p = (par); uint32_t _d;                             \
    asm volatile("{\n .reg .pred p;\n"                                                  \
        " mbarrier.try_wait.parity.relaxed.cta.shared::cta.b64 p, [%1], %2, 0x989680;\n"\
        " selp.b32 %0, 1, 0, p;\n}"                                                     \
        : "=r"(_d) : "r"(_m), "r"(_p) : "memory");                                      \
    if (!_d) {                                                                          \
        asm volatile("{\n .reg .pred P1;\n"                                             \
            "WL_%=:\n"                                                                  \
            " mbarrier.try_wait.parity.relaxed.cta.shared::cta.b64 P1, [%0], %1, 0x989680;\n" \
            " @P1 bra.uni WD_%=;\n bra.uni WL_%=;\nWD_%=:\n}"                           \
            :: "r"(_m), "r"(_p) : "memory");                                            \
    }                                                                                   \
} while (0)

#define TMA2D(dst, map, c0, c1, bar) \
    asm volatile("cp.async.bulk.tensor.2d.shared::cta.global.tile.mbarrier::complete_tx::bytes " \
                 "[%0], [%1, {%2, %3}], [%4];" \
                 :: "r"(dst), "l"(map), "r"(c0), "r"(c1), "r"(bar) : "memory")

#define LDSM4(r, addr) \
    asm volatile("ldmatrix.sync.aligned.m8n8.x4.shared.b16 {%0,%1,%2,%3}, [%4];\n" \
        : "=r"((r)[0]), "=r"((r)[1]), "=r"((r)[2]), "=r"((r)[3]) : "r"(addr))

#define LDSM4T(r0, r1, r2, r3, addr) \
    asm volatile("ldmatrix.sync.aligned.m8n8.x4.trans.shared.b16 {%0,%1,%2,%3}, [%4];\n" \
        : "=r"(r0), "=r"(r1), "=r"(r2), "=r"(r3) : "r"(addr))

#define MMA16816(d, a, b) \
    asm volatile("mma.sync.aligned.m16n8k16.row.col.f32.f16.f16.f32 " \
        "{%0,%1,%2,%3}, {%4,%5,%6,%7}, {%8,%9}, {%0,%1,%2,%3};\n" \
        : "+f"((d)[0]), "+f"((d)[1]), "+f"((d)[2]), "+f"((d)[3]) \
        : "r"((a)[0]), "r"((a)[1]), "r"((a)[2]), "r"((a)[3]), "r"((b)[0]), "r"((b)[1]))

// ---------------- AWQ int4 dequant body ----------------
__device__ __forceinline__ void dequant_body(const int* __restrict__ qw,
                                             const float* __restrict__ sc,
                                             const int* __restrict__ qz,
                                             __half* __restrict__ W,
                                             int cols, int j, int k0) {
    const int wpr = cols >> 3;
    const int grp = k0 >> 7;

    const unsigned z = ((const unsigned*)qz)[(size_t)grp * wpr + j];
    const float* srow = sc + (size_t)grp * cols + j * 8;
    const float4 s0 = *(const float4*)(srow);
    const float4 s1 = *(const float4*)(srow + 4);

    float blo[4], bhi[4], slo[4], shi[4];
#pragma unroll
    for (int p = 0; p < 4; ++p) {
        blo[p] = 8388608.0f + (float)((z >> (8 * p)) & 0xF);
        bhi[p] = 8388608.0f + 16.0f * (float)((z >> (8 * p + 4)) & 0xF);
    }
    slo[0] = s0.x; shi[0] = s0.y * 0.0625f;
    slo[1] = s0.z; shi[1] = s0.w * 0.0625f;
    slo[2] = s1.x; shi[2] = s1.y * 0.0625f;
    slo[3] = s1.z; shi[3] = s1.w * 0.0625f;

    const unsigned* qp = (const unsigned*)qw + (size_t)k0 * wpr + j;
    __half* wp = W + (size_t)k0 * cols + j * 8;

#pragma unroll
    for (int r = 0; r < 8; ++r) {
        const unsigned w = qp[(size_t)r * wpr];
        __half2 h[4];
#pragma unroll
        for (int p = 0; p < 4; ++p) {
            const unsigned t = w >> (8 * p);
            const float flo = (__uint_as_float((t & 0x0Fu) | 0x4B000000u) - blo[p]) * slo[p];
            const float fhi = (__uint_as_float((t & 0xF0u) | 0x4B000000u) - bhi[p]) * shi[p];
            h[p] = __floats2half2_rn(flo, fhi);
        }
        *(uint4*)(wp + (size_t)r * cols) = *(uint4*)h;
    }
}

// ---------------- merged prep: f2h + 3 dequants in one launch ----------------
constexpr int NB_F2H = TT * KK / 1024;
constexpr int NB_GU  = ((II / 8 + 255) / 256) * (KK / 8);   // 3072
constexpr int NB_D   = ((OO / 8 + 255) / 256) * (II / 8);   // 2752
constexpr int NB_PREP = NB_F2H + 2 * NB_GU + NB_D;          // 25280

__global__ void prep_kernel(const float* __restrict__ x,
                            const int* __restrict__ gqw, const float* __restrict__ gsc,
                            const int* __restrict__ gqz,
                            const int* __restrict__ uqw, const float* __restrict__ usc,
                            const int* __restrict__ uqz,
                            const int* __restrict__ dqw, const float* __restrict__ dsc,
                            const int* __restrict__ dqz) {
    int b = blockIdx.x;
    const int tid = threadIdx.x;
    if (b < NB_F2H) {
        size_t i = (size_t)b * 256 + tid;
        float4 v = ((const float4*)x)[i];
        __half2* o = (__half2*)g_X;
        o[2 * i + 0] = __floats2half2_rn(v.x, v.y);
        o[2 * i + 1] = __floats2half2_rn(v.z, v.w);
        return;
    }
    b -= NB_F2H;
    if (b < NB_GU) {
        int j = (b % 6) * 256 + tid;
        if (j < II / 8) dequant_body(gqw, gsc, gqz, g_Wg, II, j, (b / 6) * 8);
        return;
    }
    b -= NB_GU;
    if (b < NB_GU) {
        int j = (b % 6) * 256 + tid;
        if (j < II / 8) dequant_body(uqw, usc, uqz, g_Wu, II, j, (b / 6) * 8);
        return;
    }
    b -= NB_GU;
    {
        int j = (b % 2) * 256 + tid;
        dequant_body(dqw, dsc, dqz, g_Wd, OO, j, (b / 2) * 8);
    }
}

// ============================================================================
// GEMM1 (fused gate+up): BM=256, 64 gate + 64 up cols, BK=64 per stage, NS=4.
// 288 threads = 8 consumer warps (4m x 2n) + 1 dedicated producer warp.
// Producer loop is decoupled from MMA scheduling: refill slack = full NS-1.
// ============================================================================
constexpr int GU_KT = KK / 64;   // 64

__global__ __launch_bounds__(288, 1) void gemm_gateup(
    const __grid_constant__ CUtensorMap mA,
    const __grid_constant__ CUtensorMap mBg,
    const __grid_constant__ CUtensorMap mBu)
{
    extern __shared__ __align__(1024) char smem[];
    const uint32_t sb = smem_u32(smem);
    const int tid  = threadIdx.x;
    const int lane = tid & 31;
    const int warp = tid >> 5;
    const int m0   = blockIdx.x * 256;
    const int n0   = blockIdx.y * 64;

    if (tid == 0) {
        for (int i = 0; i < NS; ++i) {
            MBAR_INIT(sb + i * 16, 1);      // full (tx-based)
            MBAR_INIT(sb + i * 16 + 8, 8);  // empty (one arrive per consumer warp)
        }
    }
    __syncthreads();

    if (warp == 8) {
        // ---- producer warp ----
        if (lane == 0) {
            for (int s = 0; s < GU_KT; ++s) {
                const int slot = s & (NS - 1);
                if (s >= NS) MBAR_WAIT_RLX(sb + slot * 16 + 8, (uint32_t)(((s / NS) - 1) & 1));
                uint32_t d  = sb + 1024 + (uint32_t)slot * GU_STAGE;
                uint32_t fb = sb + slot * 16;
                int k0 = s * 64;
                MBAR_EXPECT_TX(fb, GU_STAGE);
                TMA2D(d,         &mA,  k0, m0, fb);
                TMA2D(d + 32768, &mBg, n0, k0, fb);
                TMA2D(d + 40960, &mBu, n0, k0, fb);
            }
        }
        return;
    }

    // ---- consumer warps (0..7): 4(m) x 2(n) ----
    const int wm = warp & 3;
    const int wn = warp >> 2;

    float cg[4][4][4];
    float cu[4][4][4];
#pragma unroll
    for (int i = 0; i < 4; i++)
#pragma unroll
        for (int j = 0; j < 4; j++)
#pragma unroll
            for (int l = 0; l < 4; l++) { cg[i][j][l] = 0.f; cu[i][j][l] = 0.f; }

    const uint32_t xr = (uint32_t)(lane & 7) << 4;
    const uint32_t aro = (uint32_t)(wm * 64 + (lane & 15)) * 128;
    const uint32_t acb = (uint32_t)((lane >> 4) << 4);
    const uint32_t bro = (uint32_t)(lane & 15) * 128;
    const uint32_t bcb = (uint32_t)(wn * 64 + ((lane >> 4) << 4));

    for (int s = 0; s < GU_KT; ++s) {
        const int slot = s & (NS - 1);
        const uint32_t par = (uint32_t)((s / NS) & 1);
        MBAR_WAIT(sb + slot * 16, par);

        const uint32_t abase  = sb + 1024 + (uint32_t)slot * GU_STAGE;
        const uint32_t bgbase = abase + 32768;
        const uint32_t bubase = abase + 40960;

#pragma unroll
        for (int ks = 0; ks < 4; ++ks) {
            uint32_t a[4][4];
#pragma unroll
            for (int mi = 0; mi < 4; ++mi) {
                uint32_t addr = abase + aro + (uint32_t)(mi * 16 * 128) +
                                (((uint32_t)(ks * 32) + acb) ^ xr);
                LDSM4(a[mi], addr);
            }
            uint32_t bg[4][2], bu[4][2];
#pragma unroll
            for (int nh = 0; nh < 2; ++nh) {
                uint32_t off = bro + (uint32_t)(ks * 16 * 128) +
                               ((bcb + (uint32_t)(nh * 32)) ^ xr);
                LDSM4T(bg[nh * 2][0], bg[nh * 2][1], bg[nh * 2 + 1][0], bg[nh * 2 + 1][1],
                       bgbase + off);
                LDSM4T(bu[nh * 2][0], bu[nh * 2][1], bu[nh * 2 + 1][0], bu[nh * 2 + 1][1],
                       bubase + off);
            }
            if (ks == 3 && lane == 0) MBAR_ARRIVE(sb + slot * 16 + 8);
#pragma unroll
            for (int mi = 0; mi < 4; ++mi)
#pragma unroll
                for (int nj = 0; nj < 4; ++nj) {
                    MMA16816(cg[mi][nj], a[mi], bg[nj]);
                    MMA16816(cu[mi][nj], a[mi], bu[nj]);
                }
        }
    }

    // epilogue: h = silu(g) * u (warp-local)
#pragma unroll
    for (int mi = 0; mi < 4; ++mi)
#pragma unroll
        for (int nj = 0; nj < 4; ++nj) {
            int r = m0 + wm * 64 + mi * 16 + (lane >> 2);
            int c = n0 + wn * 32 + nj * 8 + (lane & 3) * 2;
            float g0 = cg[mi][nj][0], g1 = cg[mi][nj][1];
            float g2 = cg[mi][nj][2], g3 = cg[mi][nj][3];
            float u0 = cu[mi][nj][0], u1 = cu[mi][nj][1];
            float u2 = cu[mi][nj][2], u3 = cu[mi][nj][3];
            float h0 = g0 / (1.f + __expf(-g0)) * u0;
            float h1 = g1 / (1.f + __expf(-g1)) * u1;
            float h2 = g2 / (1.f + __expf(-g2)) * u2;
            float h3 = g3 / (1.f + __expf(-g3)) * u3;
            *(__half2*)(g_H + (size_t)r * II + c)       = __floats2half2_rn(h0, h1);
            *(__half2*)(g_H + (size_t)(r + 8) * II + c) = __floats2half2_rn(h2, h3);
        }
}

// ============================================================================
// GEMM2 (down): BM=256, BN=128, split-K=2, 86 stages of BK=64, NS=4.
// 288 threads = 8 consumer warps (4m x 2n, warp tile 64x64) + 1 producer warp.
// Epilogue: RED into zero-initialized out (2 commutative adds, deterministic).
// ============================================================================
constexpr int DN_KT = II / 64 / 2;   // 86

__global__ __launch_bounds__(288, 1) void gemm_down(
    const __grid_constant__ CUtensorMap mA,
    const __grid_constant__ CUtensorMap mB,
    float* __restrict__ out)
{
    extern __shared__ __align__(1024) char smem[];
    const uint32_t sb = smem_u32(smem);
    const int tid  = threadIdx.x;
    const int lane = tid & 31;
    const int warp = tid >> 5;
    const int m0   = blockIdx.x * 256;
    const int n0   = blockIdx.y * 128;
    const int kbase = blockIdx.z * DN_KT;

    if (tid == 0) {
        for (int i = 0; i < NS; ++i) {
            MBAR_INIT(sb + i * 16, 1);
            MBAR_INIT(sb + i * 16 + 8, 8);
        }
    }
    __syncthreads();

    if (warp == 8) {
        // ---- producer warp ----
        if (lane == 0) {
            for (int s = 0; s < DN_KT; ++s) {
                const int slot = s & (NS - 1);
                if (s >= NS) MBAR_WAIT_RLX(sb + slot * 16 + 8, (uint32_t)(((s / NS) - 1) & 1));
                uint32_t d  = sb + 1024 + (uint32_t)slot * DN_STAGE;
                uint32_t fb = sb + slot * 16;
                int k0 = (kbase + s) * 64;
                MBAR_EXPECT_TX(fb, DN_STAGE);
                TMA2D(d,         &mA, k0, m0,  fb);
                TMA2D(d + 32768, &mB, n0,      k0, fb);
                TMA2D(d + 40960, &mB, n0 + 64, k0, fb);
            }
        }
        return;
    }

    // ---- consumer warps (0..7): 4(m) x 2(n), warp tile 64 x 64 ----
    const int wm = warp & 3;
    const int wn = warp >> 2;

    float cc[4][8][4];
#pragma unroll
    for (int i = 0; i < 4; i++)
#pragma unroll
        for (int j = 0; j < 8; j++)
#pragma unroll
            for (int l = 0; l < 4; l++) cc[i][j][l] = 0.f;

    const uint32_t xr = (uint32_t)(lane & 7) << 4;
    const uint32_t aro = (uint32_t)(wm * 64 + (lane & 15)) * 128;
    const uint32_t acb = (uint32_t)((lane >> 4) << 4);
    const uint32_t bro = (uint32_t)(lane & 15) * 128;
    const uint32_t btile = (uint32_t)wn * 8192;
    const uint32_t bcb = (uint32_t)((lane >> 4) << 4);

    for (int s = 0; s < DN_KT; ++s) {
        const int slot = s & (NS - 1);
        const uint32_t par = (uint32_t)((s / NS) & 1);
        MBAR_WAIT(sb + slot * 16, par);

        const uint32_t abase = sb + 1024 + (uint32_t)slot * DN_STAGE;
        const uint32_t bbase = abase + 32768 + btile;

#pragma unroll
        for (int ks = 0; ks < 4; ++ks) {
            uint32_t a[4][4];
#pragma unroll
            for (int mi = 0; mi < 4; ++mi) {
                uint32_t addr = abase + aro + (uint32_t)(mi * 16 * 128) +
                                (((uint32_t)(ks * 32) + acb) ^ xr);
                LDSM4(a[mi], addr);
            }
            uint32_t b[8][2];
#pragma unroll
            for (int nh = 0; nh < 4; ++nh) {
                uint32_t addr = bbase + bro + (uint32_t)(ks * 16 * 128) +
                                ((bcb + (uint32_t)(nh * 32)) ^ xr);
                LDSM4T(b[nh * 2][0], b[nh * 2][1], b[nh * 2 + 1][0], b[nh * 2 + 1][1], addr);
            }
            if (ks == 3 && lane == 0) MBAR_ARRIVE(sb + slot * 16 + 8);
#pragma unroll
            for (int mi = 0; mi < 4; ++mi)
#pragma unroll
                for (int nj = 0; nj < 8; ++nj) MMA16816(cc[mi][nj], a[mi], b[nj]);
        }
    }

    // epilogue: RED into zero-initialized out
#pragma unroll
    for (int mi = 0; mi < 4; ++mi)
#pragma unroll
        for (int nj = 0; nj < 8; ++nj) {
            int r = m0 + wm * 64 + mi * 16 + (lane >> 2);
            int c = n0 + wn * 64 + nj * 8 + (lane & 3) * 2;
            float* p0 = out + (size_t)r * OO + c;
            float* p1 = out + (size_t)(r + 8) * OO + c;
            atomicAdd(p0 + 0, cc[mi][nj][0]);
            atomicAdd(p0 + 1, cc[mi][nj][1]);
            atomicAdd(p1 + 0, cc[mi][nj][2]);
            atomicAdd(p1 + 1, cc[mi][nj][3]);
        }
}

// ---------------- host: tensormap construction ----------------
typedef CUresult (*PFN_encode)(CUtensorMap*, CUtensorMapDataType, cuuint32_t, void*,
                               const cuuint64_t*, const cuuint64_t*, const cuuint32_t*,
                               const cuuint32_t*, CUtensorMapInterleave, CUtensorMapSwizzle,
                               CUtensorMapL2promotion, CUtensorMapFloatOOBfill);

static void make_map(PFN_encode enc, CUtensorMap* m, void* ptr,
                     unsigned long long d0, unsigned long long d1,
                     unsigned b0, unsigned b1) {
    cuuint64_t dims[2] = {d0, d1};
    cuuint64_t strides[1] = {d0 * 2};  // fp16 bytes
    cuuint32_t box[2] = {b0, b1};
    cuuint32_t es[2] = {1, 1};
    enc(m, CU_TENSOR_MAP_DATA_TYPE_FLOAT16, 2, ptr, dims, strides, box, es,
        CU_TENSOR_MAP_INTERLEAVE_NONE, CU_TENSOR_MAP_SWIZZLE_128B,
        CU_TENSOR_MAP_L2_PROMOTION_L2_128B, CU_TENSOR_MAP_FLOAT_OOB_FILL_NONE);
}

extern "C" void kernel_launch(void* const* d_in, const int* in_sizes, int n_in,
                              void* d_out, int out_size) {
    (void)in_sizes; (void)n_in;
    const float* x   = (const float*)d_in[0];
    const int*   gqw = (const int*)d_in[1];
    const float* gsc = (const float*)d_in[2];
    const int*   gqz = (const int*)d_in[3];
    const int*   uqw = (const int*)d_in[4];
    const float* usc = (const float*)d_in[5];
    const int*   uqz = (const int*)d_in[6];
    const int*   dqw = (const int*)d_in[7];
    const float* dsc = (const float*)d_in[8];
    const int*   dqz = (const int*)d_in[9];
    float* out = (float*)d_out;

    PFN_encode enc = nullptr;
    cudaDriverEntryPointQueryResult qr;
    cudaGetDriverEntryPointByVersion("cuTensorMapEncodeTiled", (void**)&enc, 12000,
                                     cudaEnableDefault, &qr);
    void *pX, *pWg, *pWu, *pWd, *pH;
    cudaGetSymbolAddress(&pX,  g_X);
    cudaGetSymbolAddress(&pWg, g_Wg);
    cudaGetSymbolAddress(&pWu, g_Wu);
    cudaGetSymbolAddress(&pWd, g_Wd);
    cudaGetSymbolAddress(&pH,  g_H);

    static CUtensorMap mX, mWg, mWu, mWd, mH;
    make_map(enc, &mX,  pX,  KK, TT, 64, 256);  // A1: X [T,K]
    make_map(enc, &mWg, pWg, II, KK, 64, 64);   // Bg: Wg [K,I]
    make_map(enc, &mWu, pWu, II, KK, 64, 64);   // Bu
    make_map(enc, &mH,  pH,  II, TT, 64, 256);  // A2: H [T,I]
    make_map(enc, &mWd, pWd, OO, II, 64, 64);   // Bd: Wd [I,O]

    // merged prep: f2h + all three dequants in one launch
    prep_kernel<<<NB_PREP, 256>>>(x, gqw, gsc, gqz, uqw, usc, uqz, dqw, dsc, dqz);

    // fused gate/up GEMM + silu*mul (TMA-fed, 8 consumer warps + 1 producer)
    cudaFuncSetAttribute(gemm_gateup, cudaFuncAttributeMaxDynamicSharedMemorySize, SMEM_BYTES);
    gemm_gateup<<<dim3(TT / 256, II / 64), 288, SMEM_BYTES>>>(mX, mWg, mWu);

    // zero the output, then down GEMM REDs both split-K halves into it
    cudaMemsetAsync(out, 0, (size_t)out_size * sizeof(float));
    cudaFuncSetAttribute(gemm_down, cudaFuncAttributeMaxDynamicSharedMemorySize, SMEM_BYTES);
    gemm_down<<<dim3(TT / 256, OO / 128, 2), 288, SMEM_BYTES>>>(mH, mWd, out);
}

// round 14
// speedup vs baseline: 1.0504x; 1.0504x over previous
#include <cuda_runtime.h>
#include <cuda_fp16.h>
#include <cuda.h>
#include <cstdint>

// Problem dims (fixed by the dataset)
constexpr int TT = 4096;    // tokens
constexpr int KK = 4096;    // in_features
constexpr int II = 11008;   // intermediate
constexpr int OO = 4096;    // out_features

constexpr int NS = 4;                    // pipeline stages
constexpr uint32_t GU_STAGE = 49152;     // A 32K | Bg 8K | Bu 8K
constexpr uint32_t DN_STAGE = 49152;     // A 32K | B0 8K | B1 8K
constexpr int SMEM_BYTES = 1024 + NS * 49152;  // 197632

// ---------------- device scratch ----------------
__device__ __align__(256) __half g_Wg[(size_t)KK * II];
__device__ __align__(256) __half g_Wu[(size_t)KK * II];
__device__ __align__(256) __half g_Wd[(size_t)II * OO];
__device__ __align__(256) __half g_X [(size_t)TT * KK];
__device__ __align__(256) __half g_H [(size_t)TT * II];

// ---------------- PTX helpers ----------------
__device__ __forceinline__ uint32_t smem_u32(const void* p) {
    return (uint32_t)__cvta_generic_to_shared(p);
}

#define MBAR_INIT(addr, cnt) \
    asm volatile("mbarrier.init.shared.b64 [%0], %1;" :: "r"(addr), "r"(cnt) : "memory")

#define MBAR_EXPECT_TX(addr, bytes) \
    asm volatile("mbarrier.arrive.expect_tx.shared.b64 _, [%0], %1;" :: "r"(addr), "r"(bytes) : "memory")

#define MBAR_ARRIVE(addr) \
    asm volatile("mbarrier.arrive.shared.b64 _, [%0];" :: "r"(addr) : "memory")

// single acquire probe, no loop: out = 1 if phase already flipped
#define MBAR_POLL(addr, par, out) \
    asm volatile("{\n .reg .pred p;\n"                                                  \
        " mbarrier.try_wait.parity.acquire.cta.shared::cta.b64 p, [%1], %2;\n"          \
        " selp.b32 %0, 1, 0, p;\n}"                                                     \
        : "=r"(out) : "r"(addr), "r"(par) : "memory")

#define MBAR_WAIT(addr, par) do {                                                       \
    uint32_t _m = (addr); uint32_t _p = (par); uint32_t _d;                             \
    asm volatile("{\n .reg .pred p;\n"                                                  \
        " mbarrier.try_wait.parity.acquire.cta.shared::cta.b64 p, [%1], %2;\n"          \
        " selp.b32 %0, 1, 0, p;\n}"                                                     \
        : "=r"(_d) : "r"(_m), "r"(_p) : "memory");                                      \
    if (!_d) {                                                                          \
        asm volatile("{\n .reg .pred P1;\n"                                             \
            "WL_%=:\n"                                                                  \
            " mbarrier.try_wait.parity.acquire.cta.shared::cta.b64 P1, [%0], %1, 0x989680;\n" \
            " @P1 bra.uni WD_%=;\n bra.uni WL_%=;\nWD_%=:\n}"                           \
            :: "r"(_m), "r"(_p) : "memory");                                            \
    }                                                                                   \
} while (0)

#define MBAR_WAIT_RLX(addr, par) do {                                                   \
    uint32_t _m = (addr); uint32_t _p = (par); uint32_t _d;                             \
    asm volatile("{\n .reg .pred p;\n"                                                  \
        " mbarrier.try_wait.parity.relaxed.cta.shared::cta.b64 p, [%1], %2, 0x989680;\n"\
        " selp.b32 %0, 1, 0, p;\n}"                                                     \
        : "=r"(_d) : "r"(_m), "r"(_p) : "memory");                                      \
    if (!_d) {                                                                          \
        asm volatile("{\n .reg .pred P1;\n"                                             \
            "WL_%=:\n"                                                                  \
            " mbarrier.try_wait.parity.relaxed.cta.shared::cta.b64 P1, [%0], %1, 0x989680;\n" \
            " @P1 bra.uni WD_%=;\n bra.uni WL_%=;\nWD_%=:\n}"                           \
            :: "r"(_m), "r"(_p) : "memory");                                            \
    }                                                                                   \
} while (0)

#define TMA2D(dst, map, c0, c1, bar) \
    asm volatile("cp.async.bulk.tensor.2d.shared::cta.global.tile.mbarrier::complete_tx::bytes " \
                 "[%0], [%1, {%2, %3}], [%4];" \
                 :: "r"(dst), "l"(map), "r"(c0), "r"(c1), "r"(bar) : "memory")

#define LDSM4(r, addr) \
    asm volatile("ldmatrix.sync.aligned.m8n8.x4.shared.b16 {%0,%1,%2,%3}, [%4];\n" \
        : "=r"((r)[0]), "=r"((r)[1]), "=r"((r)[2]), "=r"((r)[3]) : "r"(addr))

#define LDSM4T(r0, r1, r2, r3, addr) \
    asm volatile("ldmatrix.sync.aligned.m8n8.x4.trans.shared.b16 {%0,%1,%2,%3}, [%4];\n" \
        : "=r"(r0), "=r"(r1), "=r"(r2), "=r"(r3) : "r"(addr))

#define MMA16816(d, a, b) \
    asm volatile("mma.sync.aligned.m16n8k16.row.col.f32.f16.f16.f32 " \
        "{%0,%1,%2,%3}, {%4,%5,%6,%7}, {%8,%9}, {%0,%1,%2,%3};\n" \
        : "+f"((d)[0]), "+f"((d)[1]), "+f"((d)[2]), "+f"((d)[3]) \
        : "r"((a)[0]), "r"((a)[1]), "r"((a)[2]), "r"((a)[3]), "r"((b)[0]), "r"((b)[1]))

// ---------------- AWQ int4 dequant body ----------------
__device__ __forceinline__ void dequant_body(const int* __restrict__ qw,
                                             const float* __restrict__ sc,
                                             const int* __restrict__ qz,
                                             __half* __restrict__ W,
                                             int cols, int j, int k0) {
    const int wpr = cols >> 3;
    const int grp = k0 >> 7;

    const unsigned z = ((const unsigned*)qz)[(size_t)grp * wpr + j];
    const float* srow = sc + (size_t)grp * cols + j * 8;
    const float4 s0 = *(const float4*)(srow);
    const float4 s1 = *(const float4*)(srow + 4);

    float blo[4], bhi[4], slo[4], shi[4];
#pragma unroll
    for (int p = 0; p < 4; ++p) {
        blo[p] = 8388608.0f + (float)((z >> (8 * p)) & 0xF);
        bhi[p] = 8388608.0f + 16.0f * (float)((z >> (8 * p + 4)) & 0xF);
    }
    slo[0] = s0.x; shi[0] = s0.y * 0.0625f;
    slo[1] = s0.z; shi[1] = s0.w * 0.0625f;
    slo[2] = s1.x; shi[2] = s1.y * 0.0625f;
    slo[3] = s1.z; shi[3] = s1.w * 0.0625f;

    const unsigned* qp = (const unsigned*)qw + (size_t)k0 * wpr + j;
    __half* wp = W + (size_t)k0 * cols + j * 8;

#pragma unroll
    for (int r = 0; r < 8; ++r) {
        const unsigned w = qp[(size_t)r * wpr];
        __half2 h[4];
#pragma unroll
        for (int p = 0; p < 4; ++p) {
            const unsigned t = w >> (8 * p);
            const float flo = (__uint_as_float((t & 0x0Fu) | 0x4B000000u) - blo[p]) * slo[p];
            const float fhi = (__uint_as_float((t & 0xF0u) | 0x4B000000u) - bhi[p]) * shi[p];
            h[p] = __floats2half2_rn(flo, fhi);
        }
        *(uint4*)(wp + (size_t)r * cols) = *(uint4*)h;
    }
}

// ---------------- merged prep: f2h + 3 dequants in one launch ----------------
constexpr int NB_F2H = TT * KK / 1024;
constexpr int NB_GU  = ((II / 8 + 255) / 256) * (KK / 8);   // 3072
constexpr int NB_D   = ((OO / 8 + 255) / 256) * (II / 8);   // 2752
constexpr int NB_PREP = NB_F2H + 2 * NB_GU + NB_D;          // 25280

__global__ void prep_kernel(const float* __restrict__ x,
                            const int* __restrict__ gqw, const float* __restrict__ gsc,
                            const int* __restrict__ gqz,
                            const int* __restrict__ uqw, const float* __restrict__ usc,
                            const int* __restrict__ uqz,
                            const int* __restrict__ dqw, const float* __restrict__ dsc,
                            const int* __restrict__ dqz) {
    int b = blockIdx.x;
    const int tid = threadIdx.x;
    if (b < NB_F2H) {
        size_t i = (size_t)b * 256 + tid;
        float4 v = ((const float4*)x)[i];
        __half2* o = (__half2*)g_X;
        o[2 * i + 0] = __floats2half2_rn(v.x, v.y);
        o[2 * i + 1] = __floats2half2_rn(v.z, v.w);
        return;
    }
    b -= NB_F2H;
    if (b < NB_GU) {
        int j = (b % 6) * 256 + tid;
        if (j < II / 8) dequant_body(gqw, gsc, gqz, g_Wg, II, j, (b / 6) * 8);
        return;
    }
    b -= NB_GU;
    if (b < NB_GU) {
        int j = (b % 6) * 256 + tid;
        if (j < II / 8) dequant_body(uqw, usc, uqz, g_Wu, II, j, (b / 6) * 8);
        return;
    }
    b -= NB_GU;
    {
        int j = (b % 2) * 256 + tid;
        dequant_body(dqw, dsc, dqz, g_Wd, OO, j, (b / 2) * 8);
    }
}

// ============================================================================
// GEMM1 (fused gate+up): BM=256, 64 gate + 64 up cols, BK=64 per stage, NS=4.
// 256 threads = 8 warps = 4(m) x 2(n). Warp: 64 rows x (32 gate + 32 up) cols.
// NEW: next-stage full barrier is POLLED mid-stage (shadowed by MMAs); the
// boundary wait is skipped when the poll succeeded (acquire done at poll).
// ============================================================================
constexpr int GU_KT = KK / 64;   // 64

__global__ __launch_bounds__(256, 1) void gemm_gateup(
    const __grid_constant__ CUtensorMap mA,
    const __grid_constant__ CUtensorMap mBg,
    const __grid_constant__ CUtensorMap mBu)
{
    extern __shared__ __align__(1024) char smem[];
    const uint32_t sb = smem_u32(smem);
    const int tid  = threadIdx.x;
    const int lane = tid & 31;
    const int warp = tid >> 5;
    const int wm   = warp & 3;
    const int wn   = warp >> 2;
    const int m0   = blockIdx.x * 256;
    const int n0   = blockIdx.y * 64;

    if (tid == 0) {
        for (int i = 0; i < NS; ++i) {
            MBAR_INIT(sb + i * 16, 1);      // full (tx-based)
            MBAR_INIT(sb + i * 16 + 8, 8);  // empty (one arrive per warp)
        }
    }
    __syncthreads();

#define GU_LOAD(slot, stg) do {                                     \
        uint32_t _d  = sb + 1024 + (uint32_t)(slot) * GU_STAGE;     \
        uint32_t _fb = sb + (slot) * 16;                            \
        int _k0 = (stg) * 64;                                       \
        MBAR_EXPECT_TX(_fb, GU_STAGE);                              \
        TMA2D(_d,         &mA,  _k0, m0, _fb);                      \
        TMA2D(_d + 32768, &mBg, n0,  _k0, _fb);                     \
        TMA2D(_d + 40960, &mBu, n0,  _k0, _fb);                     \
    } while (0)

    if (tid == 0) {
#pragma unroll
        for (int p = 0; p < NS; ++p) GU_LOAD(p, p);
    }

    float cg[4][4][4];
    float cu[4][4][4];
#pragma unroll
    for (int i = 0; i < 4; i++)
#pragma unroll
        for (int j = 0; j < 4; j++)
#pragma unroll
            for (int l = 0; l < 4; l++) { cg[i][j][l] = 0.f; cu[i][j][l] = 0.f; }

    const uint32_t xr = (uint32_t)(lane & 7) << 4;
    const uint32_t aro = (uint32_t)(wm * 64 + (lane & 15)) * 128;
    const uint32_t acb = (uint32_t)((lane >> 4) << 4);
    const uint32_t bro = (uint32_t)(lane & 15) * 128;
    const uint32_t bcb = (uint32_t)(wn * 64 + ((lane >> 4) << 4));

    uint32_t ready = 0;   // poll result for the upcoming stage
    for (int s = 0; s < GU_KT; ++s) {
        const int slot = s & (NS - 1);
        const uint32_t par = (uint32_t)((s / NS) & 1);
        if (!ready) MBAR_WAIT(sb + slot * 16, par);

        const uint32_t abase  = sb + 1024 + (uint32_t)slot * GU_STAGE;
        const uint32_t bgbase = abase + 32768;
        const uint32_t bubase = abase + 40960;

#pragma unroll
        for (int ks = 0; ks < 4; ++ks) {
            uint32_t a[4][4];
#pragma unroll
            for (int mi = 0; mi < 4; ++mi) {
                uint32_t addr = abase + aro + (uint32_t)(mi * 16 * 128) +
                                (((uint32_t)(ks * 32) + acb) ^ xr);
                LDSM4(a[mi], addr);
            }
            uint32_t bg[4][2], bu[4][2];
#pragma unroll
            for (int nh = 0; nh < 2; ++nh) {
                uint32_t off = bro + (uint32_t)(ks * 16 * 128) +
                               ((bcb + (uint32_t)(nh * 32)) ^ xr);
                LDSM4T(bg[nh * 2][0], bg[nh * 2][1], bg[nh * 2 + 1][0], bg[nh * 2 + 1][1],
                       bgbase + off);
                LDSM4T(bu[nh * 2][0], bu[nh * 2][1], bu[nh * 2 + 1][0], bu[nh * 2 + 1][1],
                       bubase + off);
            }
            if (ks == 3 && lane == 0) MBAR_ARRIVE(sb + slot * 16 + 8);
#pragma unroll
            for (int mi = 0; mi < 4; ++mi)
#pragma unroll
                for (int nj = 0; nj < 4; ++nj) {
                    MMA16816(cg[mi][nj], a[mi], bg[nj]);
                    MMA16816(cu[mi][nj], a[mi], bu[nj]);
                }
            // mid-stage: poll next stage's full barrier (latency shadowed by ks=2..3)
            if (ks == 1) {
                if (s + 1 < GU_KT) {
                    const int nslot = (s + 1) & (NS - 1);
                    const uint32_t npar = (uint32_t)(((s + 1) / NS) & 1);
                    MBAR_POLL(sb + nslot * 16, npar, ready);
                } else {
                    ready = 0;
                }
            }
        }

        if (tid == 0 && s + NS < GU_KT) {
            MBAR_WAIT_RLX(sb + slot * 16 + 8, par);
            GU_LOAD(slot, s + NS);
        }
    }
#undef GU_LOAD

    // epilogue: h = silu(g) * u (warp-local)
#pragma unroll
    for (int mi = 0; mi < 4; ++mi)
#pragma unroll
        for (int nj = 0; nj < 4; ++nj) {
            int r = m0 + wm * 64 + mi * 16 + (lane >> 2);
            int c = n0 + wn * 32 + nj * 8 + (lane & 3) * 2;
            float g0 = cg[mi][nj][0], g1 = cg[mi][nj][1];
            float g2 = cg[mi][nj][2], g3 = cg[mi][nj][3];
            float u0 = cu[mi][nj][0], u1 = cu[mi][nj][1];
            float u2 = cu[mi][nj][2], u3 = cu[mi][nj][3];
            float h0 = g0 / (1.f + __expf(-g0)) * u0;
            float h1 = g1 / (1.f + __expf(-g1)) * u1;
            float h2 = g2 / (1.f + __expf(-g2)) * u2;
            float h3 = g3 / (1.f + __expf(-g3)) * u3;
            *(__half2*)(g_H + (size_t)r * II + c)       = __floats2half2_rn(h0, h1);
            *(__half2*)(g_H + (size_t)(r + 8) * II + c) = __floats2half2_rn(h2, h3);
        }
}

// ============================================================================
// GEMM2 (down): BM=256, BN=128, split-K=2, 86 stages of BK=64, NS=4.
// 256 threads = 8 warps = 4(m) x 2(n). Warp tile: 64 x 64. Same hoisted poll.
// Epilogue: RED into zero-initialized out (2 commutative adds, deterministic).
// ============================================================================
constexpr int DN_KT = II / 64 / 2;   // 86

__global__ __launch_bounds__(256, 1) void gemm_down(
    const __grid_constant__ CUtensorMap mA,
    const __grid_constant__ CUtensorMap mB,
    float* __restrict__ out)
{
    extern __shared__ __align__(1024) char smem[];
    const uint32_t sb = smem_u32(smem);
    const int tid  = threadIdx.x;
    const int lane = tid & 31;
    const int warp = tid >> 5;
    const int wm   = warp & 3;
    const int wn   = warp >> 2;
    const int m0   = blockIdx.x * 256;
    const int n0   = blockIdx.y * 128;
    const int kbase = blockIdx.z * DN_KT;

    if (tid == 0) {
        for (int i = 0; i < NS; ++i) {
            MBAR_INIT(sb + i * 16, 1);
            MBAR_INIT(sb + i * 16 + 8, 8);
        }
    }
    __syncthreads();

#define DN_LOAD(slot, stg) do {                                     \
        uint32_t _d  = sb + 1024 + (uint32_t)(slot) * DN_STAGE;     \
        uint32_t _fb = sb + (slot) * 16;                            \
        int _k0 = (kbase + (stg)) * 64;                             \
        MBAR_EXPECT_TX(_fb, DN_STAGE);                              \
        TMA2D(_d,         &mA, _k0, m0,  _fb);                      \
        TMA2D(_d + 32768, &mB, n0,      _k0, _fb);                  \
        TMA2D(_d + 40960, &mB, n0 + 64, _k0, _fb);                  \
    } while (0)

    if (tid == 0) {
#pragma unroll
        for (int p = 0; p < NS; ++p) DN_LOAD(p, p);
    }

    float cc[4][8][4];
#pragma unroll
    for (int i = 0; i < 4; i++)
#pragma unroll
        for (int j = 0; j < 8; j++)
#pragma unroll
            for (int l = 0; l < 4; l++) cc[i][j][l] = 0.f;

    const uint32_t xr = (uint32_t)(lane & 7) << 4;
    const uint32_t aro = (uint32_t)(wm * 64 + (lane & 15)) * 128;
    const uint32_t acb = (uint32_t)((lane >> 4) << 4);
    const uint32_t bro = (uint32_t)(lane & 15) * 128;
    const uint32_t btile = (uint32_t)wn * 8192;
    const uint32_t bcb = (uint32_t)((lane >> 4) << 4);

    uint32_t ready = 0;
    for (int s = 0; s < DN_KT; ++s) {
        const int slot = s & (NS - 1);
        const uint32_t par = (uint32_t)((s / NS) & 1);
        if (!ready) MBAR_WAIT(sb + slot * 16, par);

        const uint32_t abase = sb + 1024 + (uint32_t)slot * DN_STAGE;
        const uint32_t bbase = abase + 32768 + btile;

#pragma unroll
        for (int ks = 0; ks < 4; ++ks) {
            uint32_t a[4][4];
#pragma unroll
            for (int mi = 0; mi < 4; ++mi) {
                uint32_t addr = abase + aro + (uint32_t)(mi * 16 * 128) +
                                (((uint32_t)(ks * 32) + acb) ^ xr);
                LDSM4(a[mi], addr);
            }
            uint32_t b[8][2];
#pragma unroll
            for (int nh = 0; nh < 4; ++nh) {
                uint32_t addr = bbase + bro + (uint32_t)(ks * 16 * 128) +
                                ((bcb + (uint32_t)(nh * 32)) ^ xr);
                LDSM4T(b[nh * 2][0], b[nh * 2][1], b[nh * 2 + 1][0], b[nh * 2 + 1][1], addr);
            }
            if (ks == 3 && lane == 0) MBAR_ARRIVE(sb + slot * 16 + 8);
#pragma unroll
            for (int mi = 0; mi < 4; ++mi)
#pragma unroll
                for (int nj = 0; nj < 8; ++nj) MMA16816(cc[mi][nj], a[mi], b[nj]);
            if (ks == 1) {
                if (s + 1 < DN_KT) {
                    const int nslot = (s + 1) & (NS - 1);
                    const uint32_t npar = (uint32_t)(((s + 1) / NS) & 1);
                    MBAR_POLL(sb + nslot * 16, npar, ready);
                } else {
                    ready = 0;
                }
            }
        }

        if (tid == 0 && s + NS < DN_KT) {
            MBAR_WAIT_RLX(sb + slot * 16 + 8, par);
            DN_LOAD(slot, s + NS);
        }
    }
#undef DN_LOAD

    // epilogue: RED into zero-initialized out
#pragma unroll
    for (int mi = 0; mi < 4; ++mi)
#pragma unroll
        for (int nj = 0; nj < 8; ++nj) {
            int r = m0 + wm * 64 + mi * 16 + (lane >> 2);
            int c = n0 + wn * 64 + nj * 8 + (lane & 3) * 2;
            float* p0 = out + (size_t)r * OO + c;
            float* p1 = out + (size_t)(r + 8) * OO + c;
            atomicAdd(p0 + 0, cc[mi][nj][0]);
            atomicAdd(p0 + 1, cc[mi][nj][1]);
            atomicAdd(p1 + 0, cc[mi][nj][2]);
            atomicAdd(p1 + 1, cc[mi][nj][3]);
        }
}

// ---------------- host: tensormap construction ----------------
typedef CUresult (*PFN_encode)(CUtensorMap*, CUtensorMapDataType, cuuint32_t, void*,
                               const cuuint64_t*, const cuuint64_t*, const cuuint32_t*,
                               const cuuint32_t*, CUtensorMapInterleave, CUtensorMapSwizzle,
                               CUtensorMapL2promotion, CUtensorMapFloatOOBfill);

static void make_map(PFN_encode enc, CUtensorMap* m, void* ptr,
                     unsigned long long d0, unsigned long long d1,
                     unsigned b0, unsigned b1) {
    cuuint64_t dims[2] = {d0, d1};
    cuuint64_t strides[1] = {d0 * 2};  // fp16 bytes
    cuuint32_t box[2] = {b0, b1};
    cuuint32_t es[2] = {1, 1};
    enc(m, CU_TENSOR_MAP_DATA_TYPE_FLOAT16, 2, ptr, dims, strides, box, es,
        CU_TENSOR_MAP_INTERLEAVE_NONE, CU_TENSOR_MAP_SWIZZLE_128B,
        CU_TENSOR_MAP_L2_PROMOTION_L2_128B, CU_TENSOR_MAP_FLOAT_OOB_FILL_NONE);
}

extern "C" void kernel_launch(void* const* d_in, const int* in_sizes, int n_in,
                              void* d_out, int out_size) {
    (void)in_sizes; (void)n_in;
    const float* x   = (const float*)d_in[0];
    const int*   gqw = (const int*)d_in[1];
    const float* gsc = (const float*)d_in[2];
    const int*   gqz = (const int*)d_in[3];
    const int*   uqw = (const int*)d_in[4];
    const float* usc = (const float*)d_in[5];
    const int*   uqz = (const int*)d_in[6];
    const int*   dqw = (const int*)d_in[7];
    const float* dsc = (const float*)d_in[8];
    const int*   dqz = (const int*)d_in[9];
    float* out = (float*)d_out;

    PFN_encode enc = nullptr;
    cudaDriverEntryPointQueryResult qr;
    cudaGetDriverEntryPointByVersion("cuTensorMapEncodeTiled", (void**)&enc, 12000,
                                     cudaEnableDefault, &qr);
    void *pX, *pWg, *pWu, *pWd, *pH;
    cudaGetSymbolAddress(&pX,  g_X);
    cudaGetSymbolAddress(&pWg, g_Wg);
    cudaGetSymbolAddress(&pWu, g_Wu);
    cudaGetSymbolAddress(&pWd, g_Wd);
    cudaGetSymbolAddress(&pH,  g_H);

    static CUtensorMap mX, mWg, mWu, mWd, mH;
    make_map(enc, &mX,  pX,  KK, TT, 64, 256);  // A1: X [T,K]
    make_map(enc, &mWg, pWg, II, KK, 64, 64);   // Bg: Wg [K,I]
    make_map(enc, &mWu, pWu, II, KK, 64, 64);   // Bu
    make_map(enc, &mH,  pH,  II, TT, 64, 256);  // A2: H [T,I]
    make_map(enc, &mWd, pWd, OO, II, 64, 64);   // Bd: Wd [I,O]

    // merged prep: f2h + all three dequants in one launch
    prep_kernel<<<NB_PREP, 256>>>(x, gqw, gsc, gqz, uqw, usc, uqz, dqw, dsc, dqz);

    // fused gate/up GEMM + silu*mul (TMA-fed, 8 warps, hoisted barrier poll)
    cudaFuncSetAttribute(gemm_gateup, cudaFuncAttributeMaxDynamicSharedMemorySize, SMEM_BYTES);
    gemm_gateup<<<dim3(TT / 256, II / 64), 256, SMEM_BYTES>>>(mX, mWg, mWu);

    // zero the output, then down GEMM REDs both split-K halves into it
    cudaMemsetAsync(out, 0, (size_t)out_size * sizeof(float));
    cudaFuncSetAttribute(gemm_down, cudaFuncAttributeMaxDynamicSharedMemorySize, SMEM_BYTES);
    gemm_down<<<dim3(TT / 256, OO / 128, 2), 256, SMEM_BYTES>>>(mH, mWd, out);
}

// round 15
// speedup vs baseline: 1.0628x; 1.0119x over previous
#include <cuda_runtime.h>
#include <cuda_fp16.h>
#include <cuda.h>
#include <cstdint>

// Problem dims (fixed by the dataset)
constexpr int TT = 4096;    // tokens
constexpr int KK = 4096;    // in_features
constexpr int II = 11008;   // intermediate
constexpr int OO = 4096;    // out_features

constexpr int NS = 4;                    // pipeline stages
constexpr uint32_t GU_STAGE = 49152;     // A 32K | Bg 8K | Bu 8K
constexpr uint32_t DN_STAGE = 49152;     // A 32K | B0 8K | B1 8K
constexpr int SMEM_BYTES = 1024 + NS * 49152;  // 197632

// ---------------- device scratch ----------------
__device__ __align__(256) __half g_Wg[(size_t)KK * II];
__device__ __align__(256) __half g_Wu[(size_t)KK * II];
__device__ __align__(256) __half g_Wd[(size_t)II * OO];
__device__ __align__(256) __half g_X [(size_t)TT * KK];
__device__ __align__(256) __half g_H [(size_t)TT * II];

// ---------------- PTX helpers ----------------
__device__ __forceinline__ uint32_t smem_u32(const void* p) {
    return (uint32_t)__cvta_generic_to_shared(p);
}

#define MBAR_INIT(addr, cnt) \
    asm volatile("mbarrier.init.shared.b64 [%0], %1;" :: "r"(addr), "r"(cnt) : "memory")

#define MBAR_EXPECT_TX(addr, bytes) \
    asm volatile("mbarrier.arrive.expect_tx.shared.b64 _, [%0], %1;" :: "r"(addr), "r"(bytes) : "memory")

#define MBAR_ARRIVE(addr) \
    asm volatile("mbarrier.arrive.shared.b64 _, [%0];" :: "r"(addr) : "memory")

// single acquire probe, no loop: out = 1 if phase already flipped
#define MBAR_POLL(addr, par, out) \
    asm volatile("{\n .reg .pred p;\n"                                                  \
        " mbarrier.try_wait.parity.acquire.cta.shared::cta.b64 p, [%1], %2;\n"          \
        " selp.b32 %0, 1, 0, p;\n}"                                                     \
        : "=r"(out) : "r"(addr), "r"(par) : "memory")

#define MBAR_WAIT(addr, par) do {                                                       \
    uint32_t _m = (addr); uint32_t _p = (par); uint32_t _d;                             \
    asm volatile("{\n .reg .pred p;\n"                                                  \
        " mbarrier.try_wait.parity.acquire.cta.shared::cta.b64 p, [%1], %2;\n"          \
        " selp.b32 %0, 1, 0, p;\n}"                                                     \
        : "=r"(_d) : "r"(_m), "r"(_p) : "memory");                                      \
    if (!_d) {                                                                          \
        asm volatile("{\n .reg .pred P1;\n"                                             \
            "WL_%=:\n"                                                                  \
            " mbarrier.try_wait.parity.acquire.cta.shared::cta.b64 P1, [%0], %1, 0x989680;\n" \
            " @P1 bra.uni WD_%=;\n bra.uni WL_%=;\nWD_%=:\n}"                           \
            :: "r"(_m), "r"(_p) : "memory");                                            \
    }                                                                                   \
} while (0)

#define MBAR_WAIT_RLX(addr, par) do {                                                   \
    uint32_t _m = (addr); uint32_t _p = (par); uint32_t _d;                             \
    asm volatile("{\n .reg .pred p;\n"                                                  \
        " mbarrier.try_wait.parity.relaxed.cta.shared::cta.b64 p, [%1], %2, 0x989680;\n"\
        " selp.b32 %0, 1, 0, p;\n}"                                                     \
        : "=r"(_d) : "r"(_m), "r"(_p) : "memory");                                      \
    if (!_d) {                                                                          \
        asm volatile("{\n .reg .pred P1;\n"                                             \
            "WL_%=:\n"                                                                  \
            " mbarrier.try_wait.parity.relaxed.cta.shared::cta.b64 P1, [%0], %1, 0x989680;\n" \
            " @P1 bra.uni WD_%=;\n bra.uni WL_%=;\nWD_%=:\n}"                           \
            :: "r"(_m), "r"(_p) : "memory");                                            \
    }                                                                                   \
} while (0)

#define TMA2D(dst, map, c0, c1, bar) \
    asm volatile("cp.async.bulk.tensor.2d.shared::cta.global.tile.mbarrier::complete_tx::bytes " \
                 "[%0], [%1, {%2, %3}], [%4];" \
                 :: "r"(dst), "l"(map), "r"(c0), "r"(c1), "r"(bar) : "memory")

#define LDSM4(r, addr) \
    asm volatile("ldmatrix.sync.aligned.m8n8.x4.shared.b16 {%0,%1,%2,%3}, [%4];\n" \
        : "=r"((r)[0]), "=r"((r)[1]), "=r"((r)[2]), "=r"((r)[3]) : "r"(addr))

#define LDSM4T(r0, r1, r2, r3, addr) \
    asm volatile("ldmatrix.sync.aligned.m8n8.x4.trans.shared.b16 {%0,%1,%2,%3}, [%4];\n" \
        : "=r"(r0), "=r"(r1), "=r"(r2), "=r"(r3) : "r"(addr))

#define MMA16816(d, a, b) \
    asm volatile("mma.sync.aligned.m16n8k16.row.col.f32.f16.f16.f32 " \
        "{%0,%1,%2,%3}, {%4,%5,%6,%7}, {%8,%9}, {%0,%1,%2,%3};\n" \
        : "+f"((d)[0]), "+f"((d)[1]), "+f"((d)[2]), "+f"((d)[3]) \
        : "r"((a)[0]), "r"((a)[1]), "r"((a)[2]), "r"((a)[3]), "r"((b)[0]), "r"((b)[1]))

// ---------------- AWQ int4 dequant body ----------------
__device__ __forceinline__ void dequant_body(const int* __restrict__ qw,
                                             const float* __restrict__ sc,
                                             const int* __restrict__ qz,
                                             __half* __restrict__ W,
                                             int cols, int j, int k0) {
    const int wpr = cols >> 3;
    const int grp = k0 >> 7;

    const unsigned z = ((const unsigned*)qz)[(size_t)grp * wpr + j];
    const float* srow = sc + (size_t)grp * cols + j * 8;
    const float4 s0 = *(const float4*)(srow);
    const float4 s1 = *(const float4*)(srow + 4);

    float blo[4], bhi[4], slo[4], shi[4];
#pragma unroll
    for (int p = 0; p < 4; ++p) {
        blo[p] = 8388608.0f + (float)((z >> (8 * p)) & 0xF);
        bhi[p] = 8388608.0f + 16.0f * (float)((z >> (8 * p + 4)) & 0xF);
    }
    slo[0] = s0.x; shi[0] = s0.y * 0.0625f;
    slo[1] = s0.z; shi[1] = s0.w * 0.0625f;
    slo[2] = s1.x; shi[2] = s1.y * 0.0625f;
    slo[3] = s1.z; shi[3] = s1.w * 0.0625f;

    const unsigned* qp = (const unsigned*)qw + (size_t)k0 * wpr + j;
    __half* wp = W + (size_t)k0 * cols + j * 8;

#pragma unroll
    for (int r = 0; r < 8; ++r) {
        const unsigned w = qp[(size_t)r * wpr];
        __half2 h[4];
#pragma unroll
        for (int p = 0; p < 4; ++p) {
            const unsigned t = w >> (8 * p);
            const float flo = (__uint_as_float((t & 0x0Fu) | 0x4B000000u) - blo[p]) * slo[p];
            const float fhi = (__uint_as_float((t & 0xF0u) | 0x4B000000u) - bhi[p]) * shi[p];
            h[p] = __floats2half2_rn(flo, fhi);
        }
        *(uint4*)(wp + (size_t)r * cols) = *(uint4*)h;
    }
}

// ---------------- prep: f2h + gate/up dequants ONLY (down-dequant moved
// into the gateup kernel's tail blocks) ----------------
constexpr int NB_F2H = TT * KK / 1024;                      // 16384
constexpr int NB_GU  = ((II / 8 + 255) / 256) * (KK / 8);   // 3072
constexpr int NB_PREP = NB_F2H + 2 * NB_GU;                 // 22528

__global__ void prep_kernel(const float* __restrict__ x,
                            const int* __restrict__ gqw, const float* __restrict__ gsc,
                            const int* __restrict__ gqz,
                            const int* __restrict__ uqw, const float* __restrict__ usc,
                            const int* __restrict__ uqz) {
    int b = blockIdx.x;
    const int tid = threadIdx.x;
    if (b < NB_F2H) {
        size_t i = (size_t)b * 256 + tid;
        float4 v = ((const float4*)x)[i];
        __half2* o = (__half2*)g_X;
        o[2 * i + 0] = __floats2half2_rn(v.x, v.y);
        o[2 * i + 1] = __floats2half2_rn(v.z, v.w);
        return;
    }
    b -= NB_F2H;
    if (b < NB_GU) {
        int j = (b % 6) * 256 + tid;
        if (j < II / 8) dequant_body(gqw, gsc, gqz, g_Wg, II, j, (b / 6) * 8);
        return;
    }
    b -= NB_GU;
    {
        int j = (b % 6) * 256 + tid;
        if (j < II / 8) dequant_body(uqw, usc, uqz, g_Wu, II, j, (b / 6) * 8);
    }
}

// ============================================================================
// GEMM1 (fused gate+up): BM=256, 64 gate + 64 up cols, BK=64 per stage, NS=4.
// 256 threads = 8 warps = 4(m) x 2(n). Hoisted next-stage barrier poll (R14).
// 1D grid with TAIL-WORK blocks appended after the 2752 GEMM tiles:
//   [GU_TILES, GU_TILES+NB_D)      : down-weight dequant (g_Wd)
//   [GU_TILES+NB_D, +NB_Z)         : zero the output for the RED epilogue
// These launch last and absorb the 59%-occupancy final wave. Kernel-boundary
// ordering guarantees both complete before gemm_down starts.
// ============================================================================
constexpr int GU_KT    = KK / 64;                           // 64
constexpr int GU_TILES = (TT / 256) * (II / 64);            // 2752
constexpr int NB_D     = ((OO / 8 + 255) / 256) * (II / 8); // 2752
constexpr int NB_Z     = 1024;                              // x 64KB = 64MB zeroed
constexpr int GU_GRID  = GU_TILES + NB_D + NB_Z;            // 6528

__global__ __launch_bounds__(256, 1) void gemm_gateup(
    const __grid_constant__ CUtensorMap mA,
    const __grid_constant__ CUtensorMap mBg,
    const __grid_constant__ CUtensorMap mBu,
    const int* __restrict__ dqw, const float* __restrict__ dsc,
    const int* __restrict__ dqz,
    float* __restrict__ out)
{
    extern __shared__ __align__(1024) char smem[];
    const uint32_t sb = smem_u32(smem);
    const int tid  = threadIdx.x;
    const int bid  = blockIdx.x;

    if (bid >= GU_TILES) {
        int b = bid - GU_TILES;
        if (b < NB_D) {
            // down-weight dequant (same mapping as the old dequant<2> grid)
            int j = (b % 2) * 256 + tid;   // OO/8 = 512 = 2*256, always in range
            dequant_body(dqw, dsc, dqz, g_Wd, OO, j, (b / 2) * 8);
        } else {
            // zero 64KB of out per block: 16 x 256 threads x float4
            b -= NB_D;
            float4* o = (float4*)out;
            const size_t base = (size_t)b * 4096;   // 1024 * 4096 = TT*OO/4
#pragma unroll
            for (int i = 0; i < 16; ++i)
                o[base + i * 256 + tid] = make_float4(0.f, 0.f, 0.f, 0.f);
        }
        return;
    }

    const int lane = tid & 31;
    const int warp = tid >> 5;
    const int wm   = warp & 3;
    const int wn   = warp >> 2;
    const int m0   = (bid & 15) * 256;   // 16 m-tiles
    const int n0   = (bid >> 4) * 64;    // 172 n-tiles

    if (tid == 0) {
        for (int i = 0; i < NS; ++i) {
            MBAR_INIT(sb + i * 16, 1);      // full (tx-based)
            MBAR_INIT(sb + i * 16 + 8, 8);  // empty (one arrive per warp)
        }
    }
    __syncthreads();

#define GU_LOAD(slot, stg) do {                                     \
        uint32_t _d  = sb + 1024 + (uint32_t)(slot) * GU_STAGE;     \
        uint32_t _fb = sb + (slot) * 16;                            \
        int _k0 = (stg) * 64;                                       \
        MBAR_EXPECT_TX(_fb, GU_STAGE);                              \
        TMA2D(_d,         &mA,  _k0, m0, _fb);                      \
        TMA2D(_d + 32768, &mBg, n0,  _k0, _fb);                     \
        TMA2D(_d + 40960, &mBu, n0,  _k0, _fb);                     \
    } while (0)

    if (tid == 0) {
#pragma unroll
        for (int p = 0; p < NS; ++p) GU_LOAD(p, p);
    }

    float cg[4][4][4];
    float cu[4][4][4];
#pragma unroll
    for (int i = 0; i < 4; i++)
#pragma unroll
        for (int j = 0; j < 4; j++)
#pragma unroll
            for (int l = 0; l < 4; l++) { cg[i][j][l] = 0.f; cu[i][j][l] = 0.f; }

    const uint32_t xr = (uint32_t)(lane & 7) << 4;
    const uint32_t aro = (uint32_t)(wm * 64 + (lane & 15)) * 128;
    const uint32_t acb = (uint32_t)((lane >> 4) << 4);
    const uint32_t bro = (uint32_t)(lane & 15) * 128;
    const uint32_t bcb = (uint32_t)(wn * 64 + ((lane >> 4) << 4));

    uint32_t ready = 0;   // poll result for the upcoming stage
    for (int s = 0; s < GU_KT; ++s) {
        const int slot = s & (NS - 1);
        const uint32_t par = (uint32_t)((s / NS) & 1);
        if (!ready) MBAR_WAIT(sb + slot * 16, par);

        const uint32_t abase  = sb + 1024 + (uint32_t)slot * GU_STAGE;
        const uint32_t bgbase = abase + 32768;
        const uint32_t bubase = abase + 40960;

#pragma unroll
        for (int ks = 0; ks < 4; ++ks) {
            uint32_t a[4][4];
#pragma unroll
            for (int mi = 0; mi < 4; ++mi) {
                uint32_t addr = abase + aro + (uint32_t)(mi * 16 * 128) +
                                (((uint32_t)(ks * 32) + acb) ^ xr);
                LDSM4(a[mi], addr);
            }
            uint32_t bg[4][2], bu[4][2];
#pragma unroll
            for (int nh = 0; nh < 2; ++nh) {
                uint32_t off = bro + (uint32_t)(ks * 16 * 128) +
                               ((bcb + (uint32_t)(nh * 32)) ^ xr);
                LDSM4T(bg[nh * 2][0], bg[nh * 2][1], bg[nh * 2 + 1][0], bg[nh * 2 + 1][1],
                       bgbase + off);
                LDSM4T(bu[nh * 2][0], bu[nh * 2][1], bu[nh * 2 + 1][0], bu[nh * 2 + 1][1],
                       bubase + off);
            }
            if (ks == 3 && lane == 0) MBAR_ARRIVE(sb + slot * 16 + 8);
#pragma unroll
            for (int mi = 0; mi < 4; ++mi)
#pragma unroll
                for (int nj = 0; nj < 4; ++nj) {
                    MMA16816(cg[mi][nj], a[mi], bg[nj]);
                    MMA16816(cu[mi][nj], a[mi], bu[nj]);
                }
            if (ks == 1) {
                if (s + 1 < GU_KT) {
                    const int nslot = (s + 1) & (NS - 1);
                    const uint32_t npar = (uint32_t)(((s + 1) / NS) & 1);
                    MBAR_POLL(sb + nslot * 16, npar, ready);
                } else {
                    ready = 0;
                }
            }
        }

        if (tid == 0 && s + NS < GU_KT) {
            MBAR_WAIT_RLX(sb + slot * 16 + 8, par);
            GU_LOAD(slot, s + NS);
        }
    }
#undef GU_LOAD

    // epilogue: h = silu(g) * u (warp-local)
#pragma unroll
    for (int mi = 0; mi < 4; ++mi)
#pragma unroll
        for (int nj = 0; nj < 4; ++nj) {
            int r = m0 + wm * 64 + mi * 16 + (lane >> 2);
            int c = n0 + wn * 32 + nj * 8 + (lane & 3) * 2;
            float g0 = cg[mi][nj][0], g1 = cg[mi][nj][1];
            float g2 = cg[mi][nj][2], g3 = cg[mi][nj][3];
            float u0 = cu[mi][nj][0], u1 = cu[mi][nj][1];
            float u2 = cu[mi][nj][2], u3 = cu[mi][nj][3];
            float h0 = g0 / (1.f + __expf(-g0)) * u0;
            float h1 = g1 / (1.f + __expf(-g1)) * u1;
            float h2 = g2 / (1.f + __expf(-g2)) * u2;
            float h3 = g3 / (1.f + __expf(-g3)) * u3;
            *(__half2*)(g_H + (size_t)r * II + c)       = __floats2half2_rn(h0, h1);
            *(__half2*)(g_H + (size_t)(r + 8) * II + c) = __floats2half2_rn(h2, h3);
        }
}

// ============================================================================
// GEMM2 (down): BM=256, BN=128, split-K=2, 86 stages of BK=64, NS=4.
// 256 threads = 8 warps = 4(m) x 2(n). Warp tile: 64 x 64. Hoisted poll.
// Epilogue: RED into out (zeroed by gateup tail blocks; 2 commutative adds).
// ============================================================================
constexpr int DN_KT = II / 64 / 2;   // 86

__global__ __launch_bounds__(256, 1) void gemm_down(
    const __grid_constant__ CUtensorMap mA,
    const __grid_constant__ CUtensorMap mB,
    float* __restrict__ out)
{
    extern __shared__ __align__(1024) char smem[];
    const uint32_t sb = smem_u32(smem);
    const int tid  = threadIdx.x;
    const int lane = tid & 31;
    const int warp = tid >> 5;
    const int wm   = warp & 3;
    const int wn   = warp >> 2;
    const int m0   = blockIdx.x * 256;
    const int n0   = blockIdx.y * 128;
    const int kbase = blockIdx.z * DN_KT;

    if (tid == 0) {
        for (int i = 0; i < NS; ++i) {
            MBAR_INIT(sb + i * 16, 1);
            MBAR_INIT(sb + i * 16 + 8, 8);
        }
    }
    __syncthreads();

#define DN_LOAD(slot, stg) do {                                     \
        uint32_t _d  = sb + 1024 + (uint32_t)(slot) * DN_STAGE;     \
        uint32_t _fb = sb + (slot) * 16;                            \
        int _k0 = (kbase + (stg)) * 64;                             \
        MBAR_EXPECT_TX(_fb, DN_STAGE);                              \
        TMA2D(_d,         &mA, _k0, m0,  _fb);                      \
        TMA2D(_d + 32768, &mB, n0,      _k0, _fb);                  \
        TMA2D(_d + 40960, &mB, n0 + 64, _k0, _fb);                  \
    } while (0)

    if (tid == 0) {
#pragma unroll
        for (int p = 0; p < NS; ++p) DN_LOAD(p, p);
    }

    float cc[4][8][4];
#pragma unroll
    for (int i = 0; i < 4; i++)
#pragma unroll
        for (int j = 0; j < 8; j++)
#pragma unroll
            for (int l = 0; l < 4; l++) cc[i][j][l] = 0.f;

    const uint32_t xr = (uint32_t)(lane & 7) << 4;
    const uint32_t aro = (uint32_t)(wm * 64 + (lane & 15)) * 128;
    const uint32_t acb = (uint32_t)((lane >> 4) << 4);
    const uint32_t bro = (uint32_t)(lane & 15) * 128;
    const uint32_t btile = (uint32_t)wn * 8192;
    const uint32_t bcb = (uint32_t)((lane >> 4) << 4);

    uint32_t ready = 0;
    for (int s = 0; s < DN_KT; ++s) {
        const int slot = s & (NS - 1);
        const uint32_t par = (uint32_t)((s / NS) & 1);
        if (!ready) MBAR_WAIT(sb + slot * 16, par);

        const uint32_t abase = sb + 1024 + (uint32_t)slot * DN_STAGE;
        const uint32_t bbase = abase + 32768 + btile;

#pragma unroll
        for (int ks = 0; ks < 4; ++ks) {
            uint32_t a[4][4];
#pragma unroll
            for (int mi = 0; mi < 4; ++mi) {
                uint32_t addr = abase + aro + (uint32_t)(mi * 16 * 128) +
                                (((uint32_t)(ks * 32) + acb) ^ xr);
                LDSM4(a[mi], addr);
            }
            uint32_t b[8][2];
#pragma unroll
            for (int nh = 0; nh < 4; ++nh) {
                uint32_t addr = bbase + bro + (uint32_t)(ks * 16 * 128) +
                                ((bcb + (uint32_t)(nh * 32)) ^ xr);
                LDSM4T(b[nh * 2][0], b[nh * 2][1], b[nh * 2 + 1][0], b[nh * 2 + 1][1], addr);
            }
            if (ks == 3 && lane == 0) MBAR_ARRIVE(sb + slot * 16 + 8);
#pragma unroll
            for (int mi = 0; mi < 4; ++mi)
#pragma unroll
                for (int nj = 0; nj < 8; ++nj) MMA16816(cc[mi][nj], a[mi], b[nj]);
            if (ks == 1) {
                if (s + 1 < DN_KT) {
                    const int nslot = (s + 1) & (NS - 1);
                    const uint32_t npar = (uint32_t)(((s + 1) / NS) & 1);
                    MBAR_POLL(sb + nslot * 16, npar, ready);
                } else {
                    ready = 0;
                }
            }
        }

        if (tid == 0 && s + NS < DN_KT) {
            MBAR_WAIT_RLX(sb + slot * 16 + 8, par);
            DN_LOAD(slot, s + NS);
        }
    }
#undef DN_LOAD

    // epilogue: RED into zero-initialized out
#pragma unroll
    for (int mi = 0; mi < 4; ++mi)
#pragma unroll
        for (int nj = 0; nj < 8; ++nj) {
            int r = m0 + wm * 64 + mi * 16 + (lane >> 2);
            int c = n0 + wn * 64 + nj * 8 + (lane & 3) * 2;
            float* p0 = out + (size_t)r * OO + c;
            float* p1 = out + (size_t)(r + 8) * OO + c;
            atomicAdd(p0 + 0, cc[mi][nj][0]);
            atomicAdd(p0 + 1, cc[mi][nj][1]);
            atomicAdd(p1 + 0, cc[mi][nj][2]);
            atomicAdd(p1 + 1, cc[mi][nj][3]);
        }
}

// ---------------- host: tensormap construction ----------------
typedef CUresult (*PFN_encode)(CUtensorMap*, CUtensorMapDataType, cuuint32_t, void*,
                               const cuuint64_t*, const cuuint64_t*, const cuuint32_t*,
                               const cuuint32_t*, CUtensorMapInterleave, CUtensorMapSwizzle,
                               CUtensorMapL2promotion, CUtensorMapFloatOOBfill);

static void make_map(PFN_encode enc, CUtensorMap* m, void* ptr,
                     unsigned long long d0, unsigned long long d1,
                     unsigned b0, unsigned b1) {
    cuuint64_t dims[2] = {d0, d1};
    cuuint64_t strides[1] = {d0 * 2};  // fp16 bytes
    cuuint32_t box[2] = {b0, b1};
    cuuint32_t es[2] = {1, 1};
    enc(m, CU_TENSOR_MAP_DATA_TYPE_FLOAT16, 2, ptr, dims, strides, box, es,
        CU_TENSOR_MAP_INTERLEAVE_NONE, CU_TENSOR_MAP_SWIZZLE_128B,
        CU_TENSOR_MAP_L2_PROMOTION_L2_128B, CU_TENSOR_MAP_FLOAT_OOB_FILL_NONE);
}

extern "C" void kernel_launch(void* const* d_in, const int* in_sizes, int n_in,
                              void* d_out, int out_size) {
    (void)in_sizes; (void)n_in; (void)out_size;
    const float* x   = (const float*)d_in[0];
    const int*   gqw = (const int*)d_in[1];
    const float* gsc = (const float*)d_in[2];
    const int*   gqz = (const int*)d_in[3];
    const int*   uqw = (const int*)d_in[4];
    const float* usc = (const float*)d_in[5];
    const int*   uqz = (const int*)d_in[6];
    const int*   dqw = (const int*)d_in[7];
    const float* dsc = (const float*)d_in[8];
    const int*   dqz = (const int*)d_in[9];
    float* out = (float*)d_out;

    PFN_encode enc = nullptr;
    cudaDriverEntryPointQueryResult qr;
    cudaGetDriverEntryPointByVersion("cuTensorMapEncodeTiled", (void**)&enc, 12000,
                                     cudaEnableDefault, &qr);
    void *pX, *pWg, *pWu, *pWd, *pH;
    cudaGetSymbolAddress(&pX,  g_X);
    cudaGetSymbolAddress(&pWg, g_Wg);
    cudaGetSymbolAddress(&pWu, g_Wu);
    cudaGetSymbolAddress(&pWd, g_Wd);
    cudaGetSymbolAddress(&pH,  g_H);

    static CUtensorMap mX, mWg, mWu, mWd, mH;
    make_map(enc, &mX,  pX,  KK, TT, 64, 256);  // A1: X [T,K]
    make_map(enc, &mWg, pWg, II, KK, 64, 64);   // Bg: Wg [K,I]
    make_map(enc, &mWu, pWu, II, KK, 64, 64);   // Bu
    make_map(enc, &mH,  pH,  II, TT, 64, 256);  // A2: H [T,I]
    make_map(enc, &mWd, pWd, OO, II, 64, 64);   // Bd: Wd [I,O]

    // prep: f2h + gate/up dequants (down dequant moved into gateup tail)
    prep_kernel<<<NB_PREP, 256>>>(x, gqw, gsc, gqz, uqw, usc, uqz);

    // fused gate/up GEMM + silu*mul; tail blocks dequant g_Wd and zero out
    cudaFuncSetAttribute(gemm_gateup, cudaFuncAttributeMaxDynamicSharedMemorySize, SMEM_BYTES);
    gemm_gateup<<<GU_GRID, 256, SMEM_BYTES>>>(mX, mWg, mWu, dqw, dsc, dqz, out);

    // down GEMM REDs both split-K halves into the pre-zeroed out
    cudaFuncSetAttribute(gemm_down, cudaFuncAttributeMaxDynamicSharedMemorySize, SMEM_BYTES);
    gemm_down<<<dim3(TT / 256, OO / 128, 2), 256, SMEM_BYTES>>>(mH, mWd, out);
}